// round 1
// baseline (speedup 1.0000x reference)
#include <cuda_runtime.h>
#include <cstdint>

#define L_INPUT 165142
#define KFILT   33
#define L0      (L_INPUT - KFILT + 1)   /* 165110 */
#define RDC     32
#define SDIM    512
#define QDIM    256
#define NL      45
#define FINAL   160000
#define TT      256

// ---------------- scratch (static device globals; no allocation allowed) ----
__device__ float g_xa[(size_t)RDC * L0];
__device__ float g_xb[(size_t)RDC * L0];
__device__ float g_G [(size_t)NL * RDC * FINAL];   // gated slices, [i*32+r][u]
__device__ float g_S [(size_t)SDIM * FINAL];       // relu(skip)
__device__ float g_H [(size_t)SDIM * FINAL];       // relu(post1)
__device__ float g_Wall[SDIM * (NL * RDC)];        // packed skip weights [c][i*32+r]
__device__ float g_bsum[SDIM];                     // sum_i b_skip[i][c]

// ---------------- pack skip weights + summed bias -------------------------
__global__ __launch_bounds__(256) void pack_kernel(const float* __restrict__ wskip,
                                                   const float* __restrict__ bskip,
                                                   float* __restrict__ Wall,
                                                   float* __restrict__ bsum)
{
    int idx = blockIdx.x * 256 + threadIdx.x;
    if (idx < SDIM * NL * RDC) {
        int c = idx / (NL * RDC);
        int k = idx - c * (NL * RDC);
        int i = k >> 5;
        int r = k & 31;
        Wall[idx] = wskip[(size_t)i * (SDIM * RDC) + (size_t)c * RDC + r];
    }
    if (idx < SDIM) {
        float s = 0.f;
        #pragma unroll
        for (int i = 0; i < NL; i++) s += bskip[i * SDIM + idx];
        bsum[idx] = s;
    }
}

// ---------------- causal conv: 1 -> 32 ch, K=33 ---------------------------
__global__ __launch_bounds__(256) void causal_kernel(const float* __restrict__ x,
                                                     const float* __restrict__ w,
                                                     const float* __restrict__ b,
                                                     float* __restrict__ out)
{
    __shared__ float xsh[TT + KFILT - 1];   // 288
    __shared__ float wsh[KFILT * 32];       // [k][c]
    __shared__ float bsh[32];
    int tid = threadIdx.x;
    int t0  = blockIdx.x * TT;

    for (int i = tid; i < TT + KFILT - 1; i += 256) {
        int g = t0 + i;
        xsh[i] = (g < L_INPUT) ? x[g] : 0.f;
    }
    for (int i = tid; i < 32 * KFILT; i += 256) {
        int c = i / KFILT, k = i - c * KFILT;
        wsh[k * 32 + c] = w[i];
    }
    if (tid < 32) bsh[tid] = b[tid];
    __syncthreads();

    int c = tid & 31, lane = tid >> 5;
    for (int grp = 0; grp < 4; grp++) {
        int tl = lane * 32 + grp * 8;
        float acc[8];
        #pragma unroll
        for (int u = 0; u < 8; u++) acc[u] = bsh[c];
        #pragma unroll
        for (int k = 0; k < KFILT; k++) {
            float wv = wsh[k * 32 + c];
            #pragma unroll
            for (int u = 0; u < 8; u++) acc[u] += wv * xsh[tl + u + k];
        }
        #pragma unroll
        for (int u = 0; u < 8; u++) {
            int t = t0 + tl + u;
            if (t < L0) out[(size_t)c * L0 + t] = acc[u];
        }
    }
}

// ---------------- one dilated residual layer ------------------------------
// x1 = tanh(conv3_d(x, wt) + bt); x2 = sigmoid(conv3_d(x, ws) + bs)
// g = x1*x2 ; G[i] slice write ; xout = dense(g) + x[:, t+d]
__global__ __launch_bounds__(256) void layer_kernel(const float* __restrict__ xin,
                                                    float* __restrict__ xout,
                                                    const float* __restrict__ wt,
                                                    const float* __restrict__ bt,
                                                    const float* __restrict__ ws,
                                                    const float* __restrict__ bs,
                                                    const float* __restrict__ wd,
                                                    const float* __restrict__ bd,
                                                    float* __restrict__ Gout,
                                                    int d, int L_in, int L_out, int cut)
{
    extern __shared__ float sm[];
    const int LX = TT + 2 * d;
    float* xs  = sm;                    // 32*LX
    float* wts = xs + RDC * LX;         // [k][r][c] : 3072
    float* wss = wts + 3072;            // 3072
    float* wds = wss + 3072;            // [r][c]   : 1024
    float* gs  = wds + 1024;            // 32*TT
    float* btS = gs + RDC * TT;         // 32
    float* bsS = btS + 32;
    float* bdS = bsS + 32;

    int tid = threadIdx.x;
    int t0  = blockIdx.x * TT;

    // x tile
    for (int r = 0; r < RDC; r++) {
        const float* src = xin + (size_t)r * L_in;
        for (int tt = tid; tt < LX; tt += 256) {
            int g = t0 + tt;
            xs[r * LX + tt] = (g < L_in) ? src[g] : 0.f;
        }
    }
    // weights (transpose so lanes read consecutive c)
    for (int idx = tid; idx < 3072; idx += 256) {
        int c = idx / 96, rem = idx - c * 96, r = rem / 3, k = rem - r * 3;
        wts[(k * 32 + r) * 32 + c] = wt[idx];
        wss[(k * 32 + r) * 32 + c] = ws[idx];
    }
    for (int idx = tid; idx < 1024; idx += 256) {
        int c = idx >> 5, r = idx & 31;
        wds[r * 32 + c] = wd[idx];
    }
    if (tid < 32) { btS[tid] = bt[tid]; bsS[tid] = bs[tid]; bdS[tid] = bd[tid]; }
    __syncthreads();

    int c = tid & 31;
    int lane = tid >> 5;       // warp id; whole warp shares tl -> xs reads broadcast
    int tbase = lane * 32;

    for (int grp = 0; grp < 4; grp++) {
        int tl = tbase + grp * 8;
        float a1[8], a2[8];
        #pragma unroll
        for (int u = 0; u < 8; u++) { a1[u] = btS[c]; a2[u] = bsS[c]; }
        for (int r = 0; r < RDC; r++) {
            const float* xr = &xs[r * LX + tl];
            float w0t = wts[(0 * 32 + r) * 32 + c];
            float w1t = wts[(1 * 32 + r) * 32 + c];
            float w2t = wts[(2 * 32 + r) * 32 + c];
            float w0s = wss[(0 * 32 + r) * 32 + c];
            float w1s = wss[(1 * 32 + r) * 32 + c];
            float w2s = wss[(2 * 32 + r) * 32 + c];
            #pragma unroll
            for (int u = 0; u < 8; u++) {
                float v0 = xr[u];
                float v1 = xr[u + d];
                float v2 = xr[u + 2 * d];
                a1[u] += w0t * v0; a1[u] += w1t * v1; a1[u] += w2t * v2;
                a2[u] += w0s * v0; a2[u] += w1s * v1; a2[u] += w2s * v2;
            }
        }
        #pragma unroll
        for (int u = 0; u < 8; u++) {
            float gv = tanhf(a1[u]) * (1.f / (1.f + __expf(-a2[u])));
            gs[c * TT + tl + u] = gv;
            int t  = t0 + tl + u;
            int uo = t - cut;
            if (uo >= 0 && uo < FINAL)
                Gout[(size_t)c * FINAL + uo] = gv;
        }
    }
    __syncthreads();

    // dense 1x1 + residual
    for (int grp = 0; grp < 4; grp++) {
        int tl = tbase + grp * 8;
        float ad[8];
        #pragma unroll
        for (int u = 0; u < 8; u++) ad[u] = bdS[c];
        for (int r = 0; r < RDC; r++) {
            float wv = wds[r * 32 + c];
            const float* gr = &gs[r * TT + tl];
            #pragma unroll
            for (int u = 0; u < 8; u++) ad[u] += wv * gr[u];
        }
        #pragma unroll
        for (int u = 0; u < 8; u++) {
            int t = t0 + tl + u;
            if (t < L_out)
                xout[(size_t)c * L_out + t] = ad[u] + xs[c * LX + tl + u + d];
        }
    }
}

// ---------------- classic fp32 SIMT GEMM:  C = act(A@B + bias) ------------
// A: [M x K] row-major, B: [K x N] row-major, C: [M x N] row-major.
// Requires M%128==0, N%128==0, K%8==0 (true for all three calls).
__global__ __launch_bounds__(256) void gemm_kernel(const float* __restrict__ A,
                                                   const float* __restrict__ B,
                                                   const float* __restrict__ bias,
                                                   float* __restrict__ C,
                                                   int M, int N, int K, int do_relu)
{
    __shared__ float As[8][128];
    __shared__ float Bs[8][128];

    int bn = blockIdx.x * 128;
    int bm = blockIdx.y * 128;
    int tid = threadIdx.x;

    int arow = tid >> 1;            // 0..127
    int acol = (tid & 1) * 4;       // 0 / 4
    int brow = tid >> 5;            // 0..7
    int bcol = (tid & 31) * 4;      // 0..124

    int ty = tid >> 4, tx = tid & 15;
    int m0 = ty * 8, n0 = tx * 8;

    float acc[8][8];
    #pragma unroll
    for (int i = 0; i < 8; i++)
        #pragma unroll
        for (int j = 0; j < 8; j++) acc[i][j] = 0.f;

    for (int k0 = 0; k0 < K; k0 += 8) {
        float4 a4 = *(const float4*)(A + (size_t)(bm + arow) * K + k0 + acol);
        As[acol + 0][arow] = a4.x;
        As[acol + 1][arow] = a4.y;
        As[acol + 2][arow] = a4.z;
        As[acol + 3][arow] = a4.w;
        float4 b4 = *(const float4*)(B + (size_t)(k0 + brow) * N + bn + bcol);
        *(float4*)&Bs[brow][bcol] = b4;
        __syncthreads();

        #pragma unroll
        for (int kk = 0; kk < 8; kk++) {
            float4 av0 = *(float4*)&As[kk][m0];
            float4 av1 = *(float4*)&As[kk][m0 + 4];
            float4 bv0 = *(float4*)&Bs[kk][n0];
            float4 bv1 = *(float4*)&Bs[kk][n0 + 4];
            float a[8] = {av0.x, av0.y, av0.z, av0.w, av1.x, av1.y, av1.z, av1.w};
            float b[8] = {bv0.x, bv0.y, bv0.z, bv0.w, bv1.x, bv1.y, bv1.z, bv1.w};
            #pragma unroll
            for (int i = 0; i < 8; i++)
                #pragma unroll
                for (int j = 0; j < 8; j++) acc[i][j] += a[i] * b[j];
        }
        __syncthreads();
    }

    #pragma unroll
    for (int i = 0; i < 8; i++) {
        int m = bm + m0 + i;
        float bv = bias[m];
        float4 o0, o1;
        float v;
        v = acc[i][0] + bv; o0.x = (do_relu && v < 0.f) ? 0.f : v;
        v = acc[i][1] + bv; o0.y = (do_relu && v < 0.f) ? 0.f : v;
        v = acc[i][2] + bv; o0.z = (do_relu && v < 0.f) ? 0.f : v;
        v = acc[i][3] + bv; o0.w = (do_relu && v < 0.f) ? 0.f : v;
        v = acc[i][4] + bv; o1.x = (do_relu && v < 0.f) ? 0.f : v;
        v = acc[i][5] + bv; o1.y = (do_relu && v < 0.f) ? 0.f : v;
        v = acc[i][6] + bv; o1.z = (do_relu && v < 0.f) ? 0.f : v;
        v = acc[i][7] + bv; o1.w = (do_relu && v < 0.f) ? 0.f : v;
        *(float4*)(C + (size_t)m * N + bn + n0)     = o0;
        *(float4*)(C + (size_t)m * N + bn + n0 + 4) = o1;
    }
}

// ---------------- launch --------------------------------------------------
extern "C" void kernel_launch(void* const* d_in, const int* in_sizes, int n_in,
                              void* d_out, int out_size)
{
    const float* x        = (const float*)d_in[0];
    const float* w_causal = (const float*)d_in[1];
    const float* b_causal = (const float*)d_in[2];
    const float* w_tanh   = (const float*)d_in[3];
    const float* b_tanh   = (const float*)d_in[4];
    const float* w_sig    = (const float*)d_in[5];
    const float* b_sig    = (const float*)d_in[6];
    const float* w_skip   = (const float*)d_in[7];
    const float* b_skip   = (const float*)d_in[8];
    const float* w_dense  = (const float*)d_in[9];
    const float* b_dense  = (const float*)d_in[10];
    const float* w_post1  = (const float*)d_in[11];
    const float* b_post1  = (const float*)d_in[12];
    const float* w_post2  = (const float*)d_in[13];
    const float* b_post2  = (const float*)d_in[14];

    float *xa, *xb, *G, *S, *H, *Wall, *bsum;
    cudaGetSymbolAddress((void**)&xa,   g_xa);
    cudaGetSymbolAddress((void**)&xb,   g_xb);
    cudaGetSymbolAddress((void**)&G,    g_G);
    cudaGetSymbolAddress((void**)&S,    g_S);
    cudaGetSymbolAddress((void**)&H,    g_H);
    cudaGetSymbolAddress((void**)&Wall, g_Wall);
    cudaGetSymbolAddress((void**)&bsum, g_bsum);

    cudaFuncSetAttribute(layer_kernel,
                         cudaFuncAttributeMaxDynamicSharedMemorySize, 164 * 1024);

    pack_kernel<<<(SDIM * NL * RDC + 255) / 256, 256>>>(w_skip, b_skip, Wall, bsum);
    causal_kernel<<<(L0 + TT - 1) / TT, 256>>>(x, w_causal, b_causal, xa);

    float* cur = xa;
    float* nxt = xb;
    int L = L0;
    for (int i = 0; i < NL; i++) {
        int d    = 1 << (i % 9);
        int Lout = L - 2 * d;
        int cut  = (Lout - FINAL) / 2;
        size_t smem = ((size_t)RDC * (TT + 2 * d) + 3072 + 3072 + 1024 + RDC * TT + 96)
                      * sizeof(float);
        layer_kernel<<<(Lout + TT - 1) / TT, 256, smem>>>(
            cur, nxt,
            w_tanh  + (size_t)i * 3072, b_tanh  + i * 32,
            w_sig   + (size_t)i * 3072, b_sig   + i * 32,
            w_dense + (size_t)i * 1024, b_dense + i * 32,
            G + (size_t)i * RDC * FINAL,
            d, L, Lout, cut);
        float* t = cur; cur = nxt; nxt = t;
        L = Lout;
    }

    // skip GEMM: S = relu(Wall @ G + bsum)   (512 x 1440 x 160000)
    gemm_kernel<<<dim3(FINAL / 128, SDIM / 128), 256>>>(Wall, G, bsum, S,
                                                        SDIM, FINAL, NL * RDC, 1);
    // post1: H = relu(W1 @ S + b1)           (512 x 512 x 160000)
    gemm_kernel<<<dim3(FINAL / 128, SDIM / 128), 256>>>(w_post1, S, b_post1, H,
                                                        SDIM, FINAL, SDIM, 1);
    // post2: out = W2 @ H + b2               (256 x 512 x 160000)
    gemm_kernel<<<dim3(FINAL / 128, QDIM / 128), 256>>>(w_post2, H, b_post2,
                                                        (float*)d_out,
                                                        QDIM, FINAL, SDIM, 0);
}

// round 3
// speedup vs baseline: 1.7436x; 1.7436x over previous
#include <cuda_runtime.h>
#include <cuda_fp16.h>
#include <cstdint>

#define L_INPUT 165142
#define KFILT   33
#define L0      (L_INPUT - KFILT + 1)   /* 165110 */
#define RDC     32
#define SDIM    512
#define QDIM    256
#define NL      45
#define FINAL   160000
#define TT      256
#define KPAD    1472                    /* 45*32=1440 padded to 64-multiple */

// ---------------- scratch (static device globals; no allocation allowed) ----
__device__ float g_xa[(size_t)RDC * L0];
__device__ float g_xb[(size_t)RDC * L0];
// time-major activation buffers, fp16 hi/lo split (zero-init, pads stay 0)
__device__ __half g_Ghi[(size_t)FINAL * KPAD];
__device__ __half g_Glo[(size_t)FINAL * KPAD];
__device__ __half g_Shi[(size_t)FINAL * SDIM];
__device__ __half g_Slo[(size_t)FINAL * SDIM];
__device__ __half g_Hhi[(size_t)FINAL * SDIM];
__device__ __half g_Hlo[(size_t)FINAL * SDIM];
// split weights
__device__ __half g_WaH[SDIM * KPAD];
__device__ __half g_WaL[SDIM * KPAD];
__device__ __half g_P1H[SDIM * SDIM];
__device__ __half g_P1L[SDIM * SDIM];
__device__ __half g_P2H[QDIM * SDIM];
__device__ __half g_P2L[QDIM * SDIM];
__device__ float g_bsum[SDIM];

// ---------------- helpers --------------------------------------------------
static __device__ __forceinline__ uint32_t smem_u32(const void* p) {
    uint32_t a;
    asm("{ .reg .u64 t; cvta.to.shared.u64 t, %1; cvt.u32.u64 %0, t; }"
        : "=r"(a) : "l"(p));
    return a;
}
static __device__ __forceinline__ void split_h(float v, __half& h, __half& l) {
    h = __float2half(v);
    l = __float2half(v - __half2float(h));
}

#define LDM4(R, a) \
    asm volatile("ldmatrix.sync.aligned.m8n8.x4.shared.b16 {%0,%1,%2,%3}, [%4];" \
        : "=r"((R)[0]), "=r"((R)[1]), "=r"((R)[2]), "=r"((R)[3]) : "r"(a))

#define MMA16816(C, A, B) \
    asm volatile("mma.sync.aligned.m16n8k16.row.col.f32.f16.f16.f32 " \
        "{%0,%1,%2,%3}, {%4,%5,%6,%7}, {%8,%9}, {%0,%1,%2,%3};" \
        : "+f"((C)[0]), "+f"((C)[1]), "+f"((C)[2]), "+f"((C)[3]) \
        : "r"((A)[0]), "r"((A)[1]), "r"((A)[2]), "r"((A)[3]), \
          "r"((B)[0]), "r"((B)[1]))

#define CPASYNC16(dst, src) \
    asm volatile("cp.async.cg.shared.global [%0], [%1], 16;" \
        :: "r"(dst), "l"(src) : "memory")

// ---------------- prep: split weights, pack skip weights, sum bias --------
__global__ __launch_bounds__(256) void prep_kernel(const float* __restrict__ wskip,
                                                   const float* __restrict__ bskip,
                                                   const float* __restrict__ wp1,
                                                   const float* __restrict__ wp2)
{
    int idx = blockIdx.x * 256 + threadIdx.x;
    if (idx < SDIM * KPAD) {
        int c = idx / KPAD, k = idx - c * KPAD;
        float v = 0.f;
        if (k < NL * RDC) {
            int i = k >> 5, r = k & 31;
            v = wskip[(size_t)i * SDIM * RDC + (size_t)c * RDC + r];
        }
        split_h(v, g_WaH[idx], g_WaL[idx]);
    }
    if (idx < SDIM * SDIM) split_h(wp1[idx], g_P1H[idx], g_P1L[idx]);
    if (idx < QDIM * SDIM) split_h(wp2[idx], g_P2H[idx], g_P2L[idx]);
    if (idx < SDIM) {
        float s = 0.f;
        #pragma unroll
        for (int i = 0; i < NL; i++) s += bskip[i * SDIM + idx];
        g_bsum[idx] = s;
    }
}

// ---------------- causal conv: 1 -> 32 ch, K=33 ---------------------------
__global__ __launch_bounds__(256) void causal_kernel(const float* __restrict__ x,
                                                     const float* __restrict__ w,
                                                     const float* __restrict__ b,
                                                     float* __restrict__ out)
{
    __shared__ float xsh[TT + KFILT - 1];
    __shared__ float wsh[KFILT * 32];
    __shared__ float bsh[32];
    int tid = threadIdx.x;
    int t0  = blockIdx.x * TT;

    for (int i = tid; i < TT + KFILT - 1; i += 256) {
        int g = t0 + i;
        xsh[i] = (g < L_INPUT) ? x[g] : 0.f;
    }
    for (int i = tid; i < 32 * KFILT; i += 256) {
        int c = i / KFILT, k = i - c * KFILT;
        wsh[k * 32 + c] = w[i];
    }
    if (tid < 32) bsh[tid] = b[tid];
    __syncthreads();

    int c = tid & 31, lane = tid >> 5;
    for (int grp = 0; grp < 4; grp++) {
        int tl = lane * 32 + grp * 8;
        float acc[8];
        #pragma unroll
        for (int u = 0; u < 8; u++) acc[u] = bsh[c];
        #pragma unroll
        for (int k = 0; k < KFILT; k++) {
            float wv = wsh[k * 32 + c];
            #pragma unroll
            for (int u = 0; u < 8; u++) acc[u] += wv * xsh[tl + u + k];
        }
        #pragma unroll
        for (int u = 0; u < 8; u++) {
            int t = t0 + tl + u;
            if (t < L0) out[(size_t)c * L0 + t] = acc[u];
        }
    }
}

// ---------------- one dilated residual layer ------------------------------
__global__ __launch_bounds__(256) void layer_kernel(const float* __restrict__ xin,
                                                    float* __restrict__ xout,
                                                    const float* __restrict__ wt,
                                                    const float* __restrict__ bt,
                                                    const float* __restrict__ ws,
                                                    const float* __restrict__ bs,
                                                    const float* __restrict__ wd,
                                                    const float* __restrict__ bd,
                                                    __half* __restrict__ Gh,
                                                    __half* __restrict__ Gl,
                                                    int d, int L_in, int L_out, int cut)
{
    extern __shared__ float sm[];
    const int LX = TT + 2 * d;
    float* xs  = sm;
    float* wts = xs + RDC * LX;
    float* wss = wts + 3072;
    float* wds = wss + 3072;
    float* btS = wds + 1024;
    float* bsS = btS + 32;
    float* bdS = bsS + 32;

    int tid = threadIdx.x;
    int t0  = blockIdx.x * TT;

    for (int r = 0; r < RDC; r++) {
        const float* src = xin + (size_t)r * L_in;
        for (int tt = tid; tt < LX; tt += 256) {
            int g = t0 + tt;
            xs[r * LX + tt] = (g < L_in) ? src[g] : 0.f;
        }
    }
    for (int idx = tid; idx < 3072; idx += 256) {
        int c = idx / 96, rem = idx - c * 96, r = rem / 3, k = rem - r * 3;
        wts[(k * 32 + r) * 32 + c] = wt[idx];
        wss[(k * 32 + r) * 32 + c] = ws[idx];
    }
    for (int idx = tid; idx < 1024; idx += 256) {
        int c = idx >> 5, r = idx & 31;
        wds[r * 32 + c] = wd[idx];
    }
    if (tid < 32) { btS[tid] = bt[tid]; bsS[tid] = bs[tid]; bdS[tid] = bd[tid]; }
    __syncthreads();

    int c = tid & 31;          // lane == channel
    int tbase = (tid >> 5) * 32;

    for (int grp = 0; grp < 4; grp++) {
        int tl = tbase + grp * 8;
        float a1[8], a2[8];
        #pragma unroll
        for (int u = 0; u < 8; u++) { a1[u] = btS[c]; a2[u] = bsS[c]; }
        for (int r = 0; r < RDC; r++) {
            const float* xr = &xs[r * LX + tl];
            float w0t = wts[(0 * 32 + r) * 32 + c];
            float w1t = wts[(1 * 32 + r) * 32 + c];
            float w2t = wts[(2 * 32 + r) * 32 + c];
            float w0s = wss[(0 * 32 + r) * 32 + c];
            float w1s = wss[(1 * 32 + r) * 32 + c];
            float w2s = wss[(2 * 32 + r) * 32 + c];
            #pragma unroll
            for (int u = 0; u < 8; u++) {
                float v0 = xr[u];
                float v1 = xr[u + d];
                float v2 = xr[u + 2 * d];
                a1[u] += w0t * v0; a1[u] += w1t * v1; a1[u] += w2t * v2;
                a2[u] += w0s * v0; a2[u] += w1s * v1; a2[u] += w2s * v2;
            }
        }
        float g[8];
        #pragma unroll
        for (int u = 0; u < 8; u++) {
            // tanh(a) = 2*sigmoid(2a)-1 via fast exp/div
            float th = __fdividef(2.f, 1.f + __expf(-2.f * a1[u])) - 1.f;
            float sg = __fdividef(1.f, 1.f + __expf(-a2[u]));
            g[u] = th * sg;
            int t  = t0 + tl + u;
            int uo = t - cut;
            if (uo >= 0 && uo < FINAL) {
                __half h, l;
                split_h(g[u], h, l);
                Gh[(size_t)uo * KPAD + c] = h;
                Gl[(size_t)uo * KPAD + c] = l;
            }
        }
        // dense 1x1 via warp shfl (lane r broadcasts g[r])
        float ad[8];
        #pragma unroll
        for (int u = 0; u < 8; u++) ad[u] = bdS[c];
        for (int r = 0; r < RDC; r++) {
            float wv = wds[r * 32 + c];
            #pragma unroll
            for (int u = 0; u < 8; u++)
                ad[u] += wv * __shfl_sync(0xffffffffu, g[u], r);
        }
        #pragma unroll
        for (int u = 0; u < 8; u++) {
            int t = t0 + tl + u;
            if (t < L_out)
                xout[(size_t)c * L_out + t] = ad[u] + xs[c * LX + tl + u + d];
        }
    }
}

// ---------------- mma.sync split-fp16 GEMM --------------------------------
// D[m][n] = sum_k A[m][k]*B[n][k], A/B = hi+lo fp16 (3-term split products).
// CTA 128x128, 512 threads, warp tile 32x32, K-chunks of 64, cp.async 2-stage.
// mode=1: v=relu(v+bias) -> fp16 hi/lo into Ch/Cl (time-major, stride Cstr)
// mode=0: v=v+bias       -> fp32 into Cf (channel-major, stride FINAL)
#define GSMEM (2 * 65536)
__global__ __launch_bounds__(512, 1) void gemm_mma(
    const __half* __restrict__ Ah, const __half* __restrict__ Al,
    const __half* __restrict__ Bh, const __half* __restrict__ Bl,
    const float* __restrict__ bias, int Kstr, int NC, int mode,
    __half* __restrict__ Ch, __half* __restrict__ Cl, int Cstr,
    float* __restrict__ Cf)
{
    extern __shared__ char smem[];
    const uint32_t sb = smem_u32(smem);
    const int tid = threadIdx.x;
    const int m0 = blockIdx.x << 7, n0 = blockIdx.y << 7;
    const int lane = tid & 31;
    const int wm = (tid >> 5) & 3, wn = tid >> 7;

    float acc[8][4];
    #pragma unroll
    for (int i = 0; i < 8; i++)
        #pragma unroll
        for (int j = 0; j < 4; j++) acc[i][j] = 0.f;

    // issue cp.async for chunk c into buffer c&1
    auto issue = [&](int c) {
        uint32_t buf = (c & 1) ? 65536u : 0u;
        int kc0 = c << 6;
        int rloc = tid >> 3, q = tid & 7;
        #pragma unroll
        for (int it = 0; it < 8; it++) {
            const int region = it >> 1;
            int rr = ((it & 1) << 6) + rloc;
            const __half* src;
            if      (region == 0) src = Ah + (size_t)(m0 + rr) * Kstr + kc0 + q * 8;
            else if (region == 1) src = Al + (size_t)(m0 + rr) * Kstr + kc0 + q * 8;
            else if (region == 2) src = Bh + (size_t)(n0 + rr) * Kstr + kc0 + q * 8;
            else                  src = Bl + (size_t)(n0 + rr) * Kstr + kc0 + q * 8;
            uint32_t off = (uint32_t)(rr * 128 + q * 16);
            off ^= (off >> 3) & 0x70;
            CPASYNC16(sb + buf + region * 16384u + off, src);
        }
        asm volatile("cp.async.commit_group;" ::: "memory");
    };

    issue(0);
    for (int c = 0; c < NC; c++) {
        if (c + 1 < NC) {
            issue(c + 1);
            asm volatile("cp.async.wait_group 1;" ::: "memory");
        } else {
            asm volatile("cp.async.wait_group 0;" ::: "memory");
        }
        __syncthreads();
        const uint32_t buf = sb + ((c & 1) ? 65536u : 0u);

        #pragma unroll
        for (int ks = 0; ks < 4; ks++) {
            uint32_t ah[2][4], al2[2][4], bh[4][2], bl2[4][2];
            #pragma unroll
            for (int mi = 0; mi < 2; mi++) {
                uint32_t row = wm * 32 + mi * 16 + (lane & 15);
                uint32_t ch  = ks * 2 + (lane >> 4);
                uint32_t off = row * 128 + ch * 16;
                off ^= (off >> 3) & 0x70;
                LDM4(ah[mi],  buf + off);
                LDM4(al2[mi], buf + 16384u + off);
            }
            #pragma unroll
            for (int nj = 0; nj < 2; nj++) {
                uint32_t row = wn * 32 + nj * 16 + (lane & 7) + ((lane >> 4) << 3);
                uint32_t ch  = ks * 2 + ((lane >> 3) & 1);
                uint32_t off = row * 128 + ch * 16;
                off ^= (off >> 3) & 0x70;
                uint32_t r4[4];
                LDM4(r4, buf + 32768u + off);
                bh[nj * 2][0] = r4[0]; bh[nj * 2][1] = r4[1];
                bh[nj * 2 + 1][0] = r4[2]; bh[nj * 2 + 1][1] = r4[3];
                LDM4(r4, buf + 49152u + off);
                bl2[nj * 2][0] = r4[0]; bl2[nj * 2][1] = r4[1];
                bl2[nj * 2 + 1][0] = r4[2]; bl2[nj * 2 + 1][1] = r4[3];
            }
            #pragma unroll
            for (int mi = 0; mi < 2; mi++)
                #pragma unroll
                for (int nt = 0; nt < 4; nt++) {
                    float* C = acc[mi * 4 + nt];
                    MMA16816(C, ah[mi],  bh[nt]);
                    MMA16816(C, ah[mi],  bl2[nt]);
                    MMA16816(C, al2[mi], bh[nt]);
                }
        }
        __syncthreads();
    }

    // epilogue: stage fp32 tile to smem as cs[n][m] (stride 132 -> conflict-free)
    float* cs = (float*)smem;
    #pragma unroll
    for (int mi = 0; mi < 2; mi++)
        #pragma unroll
        for (int nt = 0; nt < 4; nt++) {
            float* C = acc[mi * 4 + nt];
            int mrow = wm * 32 + mi * 16 + (lane >> 2);
            int ncol = wn * 32 + nt * 8 + 2 * (lane & 3);
            cs[ncol * 132 + mrow]           = C[0];
            cs[(ncol + 1) * 132 + mrow]     = C[1];
            cs[ncol * 132 + mrow + 8]       = C[2];
            cs[(ncol + 1) * 132 + mrow + 8] = C[3];
        }
    __syncthreads();

    if (mode) {
        #pragma unroll
        for (int it = 0; it < 16; it++) {
            int idx = it * 512 + tid;
            int n = idx >> 6, mp = idx & 63;
            float2 v2 = *(float2*)&cs[n * 132 + 2 * mp];
            float b0 = __ldg(bias + m0 + 2 * mp);
            float b1 = __ldg(bias + m0 + 2 * mp + 1);
            float v0 = fmaxf(v2.x + b0, 0.f);
            float v1 = fmaxf(v2.y + b1, 0.f);
            __half h0, l0, h1, l1;
            split_h(v0, h0, l0);
            split_h(v1, h1, l1);
            uint32_t ph = (uint32_t)__half_as_ushort(h0) |
                          ((uint32_t)__half_as_ushort(h1) << 16);
            uint32_t pl = (uint32_t)__half_as_ushort(l0) |
                          ((uint32_t)__half_as_ushort(l1) << 16);
            size_t o = (size_t)(n0 + n) * Cstr + m0 + 2 * mp;
            *(uint32_t*)(Ch + o) = ph;
            *(uint32_t*)(Cl + o) = pl;
        }
    } else {
        #pragma unroll
        for (int it = 0; it < 32; it++) {
            int idx = it * 512 + tid;
            int n = idx & 127, m = idx >> 7;
            float v = cs[n * 132 + m] + __ldg(bias + m0 + m);
            Cf[(size_t)(m0 + m) * FINAL + n0 + n] = v;
        }
    }
}

// ---------------- launch --------------------------------------------------
extern "C" void kernel_launch(void* const* d_in, const int* in_sizes, int n_in,
                              void* d_out, int out_size)
{
    const float* x        = (const float*)d_in[0];
    const float* w_causal = (const float*)d_in[1];
    const float* b_causal = (const float*)d_in[2];
    const float* w_tanh   = (const float*)d_in[3];
    const float* b_tanh   = (const float*)d_in[4];
    const float* w_sig    = (const float*)d_in[5];
    const float* b_sig    = (const float*)d_in[6];
    const float* w_skip   = (const float*)d_in[7];
    const float* b_skip   = (const float*)d_in[8];
    const float* w_dense  = (const float*)d_in[9];
    const float* b_dense  = (const float*)d_in[10];
    const float* w_post1  = (const float*)d_in[11];
    const float* b_post1  = (const float*)d_in[12];
    const float* w_post2  = (const float*)d_in[13];
    const float* b_post2  = (const float*)d_in[14];

    float *xa, *xb, *bsum;
    __half *Ghi, *Glo, *Shi, *Slo, *Hhi, *Hlo;
    __half *WaH, *WaL, *P1H, *P1L, *P2H, *P2L;
    cudaGetSymbolAddress((void**)&xa,  g_xa);
    cudaGetSymbolAddress((void**)&xb,  g_xb);
    cudaGetSymbolAddress((void**)&Ghi, g_Ghi);
    cudaGetSymbolAddress((void**)&Glo, g_Glo);
    cudaGetSymbolAddress((void**)&Shi, g_Shi);
    cudaGetSymbolAddress((void**)&Slo, g_Slo);
    cudaGetSymbolAddress((void**)&Hhi, g_Hhi);
    cudaGetSymbolAddress((void**)&Hlo, g_Hlo);
    cudaGetSymbolAddress((void**)&WaH, g_WaH);
    cudaGetSymbolAddress((void**)&WaL, g_WaL);
    cudaGetSymbolAddress((void**)&P1H, g_P1H);
    cudaGetSymbolAddress((void**)&P1L, g_P1L);
    cudaGetSymbolAddress((void**)&P2H, g_P2H);
    cudaGetSymbolAddress((void**)&P2L, g_P2L);
    cudaGetSymbolAddress((void**)&bsum, g_bsum);

    cudaFuncSetAttribute(layer_kernel,
                         cudaFuncAttributeMaxDynamicSharedMemorySize, 160 * 1024);
    cudaFuncSetAttribute(gemm_mma,
                         cudaFuncAttributeMaxDynamicSharedMemorySize, GSMEM);

    prep_kernel<<<(SDIM * KPAD + 255) / 256, 256>>>(w_skip, b_skip, w_post1, w_post2);
    causal_kernel<<<(L0 + TT - 1) / TT, 256>>>(x, w_causal, b_causal, xa);

    float* cur = xa;
    float* nxt = xb;
    int L = L0;
    for (int i = 0; i < NL; i++) {
        int d    = 1 << (i % 9);
        int Lout = L - 2 * d;
        int cut  = (Lout - FINAL) / 2;
        size_t smem = ((size_t)RDC * (TT + 2 * d) + 3072 + 3072 + 1024 + 96)
                      * sizeof(float);
        layer_kernel<<<(Lout + TT - 1) / TT, 256, smem>>>(
            cur, nxt,
            w_tanh  + (size_t)i * 3072, b_tanh  + i * 32,
            w_sig   + (size_t)i * 3072, b_sig   + i * 32,
            w_dense + (size_t)i * 1024, b_dense + i * 32,
            Ghi + i * 32, Glo + i * 32,
            d, L, Lout, cut);
        float* t = cur; cur = nxt; nxt = t;
        L = Lout;
    }

    // skip GEMM: S = relu(Wall @ G + bsum)   M=512, K=1472, N=160000
    gemm_mma<<<dim3(SDIM / 128, FINAL / 128), 512, GSMEM>>>(
        WaH, WaL, Ghi, Glo, bsum, KPAD, KPAD / 64, 1, Shi, Slo, SDIM, nullptr);
    // post1: H = relu(W1 @ S + b1)           M=512, K=512
    gemm_mma<<<dim3(SDIM / 128, FINAL / 128), 512, GSMEM>>>(
        P1H, P1L, Shi, Slo, b_post1, SDIM, SDIM / 64, 1, Hhi, Hlo, SDIM, nullptr);
    // post2: out = W2 @ H + b2               M=256, K=512, fp32 channel-major
    gemm_mma<<<dim3(QDIM / 128, FINAL / 128), 512, GSMEM>>>(
        P2H, P2L, Hhi, Hlo, b_post2, SDIM, SDIM / 64, 0, nullptr, nullptr, 0,
        (float*)d_out);
}

// round 4
// speedup vs baseline: 1.9745x; 1.1324x over previous
#include <cuda_runtime.h>
#include <cuda_fp16.h>
#include <cstdint>

#define L_INPUT 165142
#define KFILT   33
#define L0      (L_INPUT - KFILT + 1)   /* 165110 */
#define RDC     32
#define SDIM    512
#define QDIM    256
#define NL      45
#define FINAL   160000
#define KPAD    1472                    /* 45*32=1440 padded to 64-multiple */

// ---------------- scratch (static device globals; no allocation allowed) ----
__device__ float g_xa[(size_t)RDC * L0];
__device__ float g_xb[(size_t)RDC * L0];
// time-major activation buffers, fp16 hi/lo split (zero-init, pads stay 0)
__device__ __half g_Ghi[(size_t)FINAL * KPAD];
__device__ __half g_Glo[(size_t)FINAL * KPAD];
__device__ __half g_Shi[(size_t)FINAL * SDIM];
__device__ __half g_Slo[(size_t)FINAL * SDIM];
__device__ __half g_Hhi[(size_t)FINAL * SDIM];
__device__ __half g_Hlo[(size_t)FINAL * SDIM];
// split weights
__device__ __half g_WaH[SDIM * KPAD];
__device__ __half g_WaL[SDIM * KPAD];
__device__ __half g_P1H[SDIM * SDIM];
__device__ __half g_P1L[SDIM * SDIM];
__device__ __half g_P2H[QDIM * SDIM];
__device__ __half g_P2L[QDIM * SDIM];
__device__ float g_bsum[SDIM];

// ---------------- helpers --------------------------------------------------
static __device__ __forceinline__ uint32_t smem_u32(const void* p) {
    uint32_t a;
    asm("{ .reg .u64 t; cvta.to.shared.u64 t, %1; cvt.u32.u64 %0, t; }"
        : "=r"(a) : "l"(p));
    return a;
}
static __device__ __forceinline__ void split_h(float v, __half& h, __half& l) {
    h = __float2half(v);
    l = __float2half(v - __half2float(h));
}
// packed f32x2 fma (B300 FFMA2 path)
static __device__ __forceinline__ void fma2(float2& c, float2 a, float2 b) {
    unsigned long long C, A, B;
    memcpy(&C, &c, 8); memcpy(&A, &a, 8); memcpy(&B, &b, 8);
    asm("fma.rn.f32x2 %0, %1, %2, %0;" : "+l"(C) : "l"(A), "l"(B));
    memcpy(&c, &C, 8);
}
static __device__ __forceinline__ float gate_fn(float a1, float a2) {
    float th = __fdividef(2.f, 1.f + __expf(-2.f * a1)) - 1.f;
    float sg = __fdividef(1.f, 1.f + __expf(-a2));
    return th * sg;
}

#define LDM4(R, a) \
    asm volatile("ldmatrix.sync.aligned.m8n8.x4.shared.b16 {%0,%1,%2,%3}, [%4];" \
        : "=r"((R)[0]), "=r"((R)[1]), "=r"((R)[2]), "=r"((R)[3]) : "r"(a))

#define MMA16816(C, A, B) \
    asm volatile("mma.sync.aligned.m16n8k16.row.col.f32.f16.f16.f32 " \
        "{%0,%1,%2,%3}, {%4,%5,%6,%7}, {%8,%9}, {%0,%1,%2,%3};" \
        : "+f"((C)[0]), "+f"((C)[1]), "+f"((C)[2]), "+f"((C)[3]) \
        : "r"((A)[0]), "r"((A)[1]), "r"((A)[2]), "r"((A)[3]), \
          "r"((B)[0]), "r"((B)[1]))

#define CPASYNC16(dst, src) \
    asm volatile("cp.async.cg.shared.global [%0], [%1], 16;" \
        :: "r"(dst), "l"(src) : "memory")

// ---------------- prep: split weights, pack skip weights, sum bias --------
__global__ __launch_bounds__(256) void prep_kernel(const float* __restrict__ wskip,
                                                   const float* __restrict__ bskip,
                                                   const float* __restrict__ wp1,
                                                   const float* __restrict__ wp2)
{
    int idx = blockIdx.x * 256 + threadIdx.x;
    if (idx < SDIM * KPAD) {
        int c = idx / KPAD, k = idx - c * KPAD;
        float v = 0.f;
        if (k < NL * RDC) {
            int i = k >> 5, r = k & 31;
            v = wskip[(size_t)i * SDIM * RDC + (size_t)c * RDC + r];
        }
        split_h(v, g_WaH[idx], g_WaL[idx]);
    }
    if (idx < SDIM * SDIM) split_h(wp1[idx], g_P1H[idx], g_P1L[idx]);
    if (idx < QDIM * SDIM) split_h(wp2[idx], g_P2H[idx], g_P2L[idx]);
    if (idx < SDIM) {
        float s = 0.f;
        #pragma unroll
        for (int i = 0; i < NL; i++) s += bskip[i * SDIM + idx];
        g_bsum[idx] = s;
    }
}

// ---------------- causal conv: 1 -> 32 ch, K=33 ---------------------------
__global__ __launch_bounds__(256) void causal_kernel(const float* __restrict__ x,
                                                     const float* __restrict__ w,
                                                     const float* __restrict__ b,
                                                     float* __restrict__ out)
{
    __shared__ float xsh[256 + KFILT - 1];
    __shared__ float wsh[KFILT * 32];
    __shared__ float bsh[32];
    int tid = threadIdx.x;
    int t0  = blockIdx.x * 256;

    for (int i = tid; i < 256 + KFILT - 1; i += 256) {
        int g = t0 + i;
        xsh[i] = (g < L_INPUT) ? x[g] : 0.f;
    }
    for (int i = tid; i < 32 * KFILT; i += 256) {
        int c = i / KFILT, k = i - c * KFILT;
        wsh[k * 32 + c] = w[i];
    }
    if (tid < 32) bsh[tid] = b[tid];
    __syncthreads();

    int c = tid & 31, lane = tid >> 5;
    for (int grp = 0; grp < 4; grp++) {
        int tl = lane * 32 + grp * 8;
        float acc[8];
        #pragma unroll
        for (int u = 0; u < 8; u++) acc[u] = bsh[c];
        #pragma unroll
        for (int k = 0; k < KFILT; k++) {
            float wv = wsh[k * 32 + c];
            #pragma unroll
            for (int u = 0; u < 8; u++) acc[u] += wv * xsh[tl + u + k];
        }
        #pragma unroll
        for (int u = 0; u < 8; u++) {
            int t = t0 + tl + u;
            if (t < L0) out[(size_t)c * L0 + t] = acc[u];
        }
    }
}

// ---------------- one dilated residual layer (templated on dilation) ------
template<int D, int NT>
__global__ __launch_bounds__(NT, 1) void layer_kernel(
    const float* __restrict__ xin, float* __restrict__ xout,
    const float* __restrict__ wt, const float* __restrict__ bt,
    const float* __restrict__ ws, const float* __restrict__ bs,
    const float* __restrict__ wd, const float* __restrict__ bd,
    __half* __restrict__ Gh, __half* __restrict__ Gl,
    int L_in, int L_out, int cut)
{
    constexpr int LX  = NT + 2 * D;
    constexpr int LXP = LX + ((4 + 32 - (LX & 31)) & 31);   // LXP % 32 == 4
    extern __shared__ float sm[];
    float* xs  = sm;                    // 32 * LXP
    float* wts = xs + 32 * LXP;         // 3072 : [(k*32+r)*32 + c]
    float* wss = wts + 3072;            // 3072
    float* wds = wss + 3072;            // 1024 : [r*32 + c]
    float* bsh = wds + 1024;            // 96
    float* gsm = bsh + 96;              // (NT/32) * 32*34

    const int tid = threadIdx.x;
    const int t0  = blockIdx.x * NT;

    #pragma unroll 1
    for (int r = 0; r < 32; r++) {
        const float* src = xin + (size_t)r * L_in;
        for (int tt = tid; tt < LX; tt += NT) {
            int g = t0 + tt;
            xs[r * LXP + tt] = (g < L_in) ? src[g] : 0.f;
        }
    }
    for (int idx = tid; idx < 3072; idx += NT) {
        int c = idx / 96, rem = idx - c * 96, r = rem / 3, k = rem - r * 3;
        wts[(k * 32 + r) * 32 + c] = wt[idx];
        wss[(k * 32 + r) * 32 + c] = ws[idx];
    }
    for (int idx = tid; idx < 1024; idx += NT)
        wds[(idx & 31) * 32 + (idx >> 5)] = wd[idx];
    if (tid < 32) { bsh[tid] = bt[tid]; bsh[32 + tid] = bs[tid]; bsh[64 + tid] = bd[tid]; }
    __syncthreads();

    const int c  = tid & 31;            // lane == output channel
    const int wp = tid >> 5;
    const int tl = wp << 5;             // 32 time steps per warp
    float* gw = gsm + wp * (32 * 34);

    float2 a1[16], a2[16];
    {
        float b0 = bsh[c], b1 = bsh[32 + c];
        #pragma unroll
        for (int p = 0; p < 16; p++) {
            a1[p] = make_float2(b0, b0);
            a2[p] = make_float2(b1, b1);
        }
    }

    #pragma unroll 1
    for (int r = 0; r < 32; r++) {
        const float* xr = xs + r * LXP + tl;
        float2 W0t = make_float2(wts[r * 32 + c],        wts[r * 32 + c]);
        float2 W1t = make_float2(wts[(32 + r) * 32 + c], wts[(32 + r) * 32 + c]);
        float2 W2t = make_float2(wts[(64 + r) * 32 + c], wts[(64 + r) * 32 + c]);
        float2 W0s = make_float2(wss[r * 32 + c],        wss[r * 32 + c]);
        float2 W1s = make_float2(wss[(32 + r) * 32 + c], wss[(32 + r) * 32 + c]);
        float2 W2s = make_float2(wss[(64 + r) * 32 + c], wss[(64 + r) * 32 + c]);
        #pragma unroll
        for (int p = 0; p < 16; p++) {
            float2 v0 = make_float2(xr[2 * p],         xr[2 * p + 1]);
            float2 v1 = make_float2(xr[2 * p + D],     xr[2 * p + 1 + D]);
            float2 v2 = make_float2(xr[2 * p + 2 * D], xr[2 * p + 1 + 2 * D]);
            fma2(a1[p], W0t, v0); fma2(a1[p], W1t, v1); fma2(a1[p], W2t, v2);
            fma2(a2[p], W0s, v0); fma2(a2[p], W1s, v1); fma2(a2[p], W2s, v2);
        }
    }

    // activation + G write + per-warp g tile
    #pragma unroll
    for (int p = 0; p < 16; p++) {
        float g0 = gate_fn(a1[p].x, a2[p].x);
        float g1 = gate_fn(a1[p].y, a2[p].y);
        *(float2*)(gw + c * 34 + 2 * p) = make_float2(g0, g1);
        int t  = t0 + tl + 2 * p;
        int uo = t - cut;
        if (uo >= 0 && uo < FINAL) {
            __half h, l;
            split_h(g0, h, l);
            Gh[(size_t)uo * KPAD + c] = h;
            Gl[(size_t)uo * KPAD + c] = l;
        }
        uo++;
        if (uo >= 0 && uo < FINAL) {
            __half h, l;
            split_h(g1, h, l);
            Gh[(size_t)uo * KPAD + c] = h;
            Gl[(size_t)uo * KPAD + c] = l;
        }
    }
    __syncwarp();

    // dense 1x1 + residual
    float2 ad[16];
    {
        float b2 = bsh[64 + c];
        #pragma unroll
        for (int p = 0; p < 16; p++) ad[p] = make_float2(b2, b2);
    }
    #pragma unroll 1
    for (int r = 0; r < 32; r++) {
        float w = wds[r * 32 + c];
        float2 W = make_float2(w, w);
        const float* gr = gw + r * 34;
        #pragma unroll
        for (int p = 0; p < 16; p++)
            fma2(ad[p], W, *(const float2*)(gr + 2 * p));
    }
    const float* resp = xs + c * LXP + tl + D;
    float* orow = xout + (size_t)c * L_out;
    #pragma unroll
    for (int p = 0; p < 16; p++) {
        int t = t0 + tl + 2 * p;
        if (t + 1 < L_out) {
            *(float2*)(orow + t) = make_float2(ad[p].x + resp[2 * p],
                                               ad[p].y + resp[2 * p + 1]);
        } else if (t < L_out) {
            orow[t] = ad[p].x + resp[2 * p];
        }
    }
}

#define LAYER_LXP(D_, NT_) (((NT_) + 2 * (D_)) + ((4 + 32 - (((NT_) + 2 * (D_)) & 31)) & 31))
#define LAYER_SMEM(D_, NT_) ((size_t)(32 * LAYER_LXP(D_, NT_) + 3072 + 3072 + 1024 + 96 \
                              + ((NT_) / 32) * 32 * 34) * 4)

// ---------------- mma.sync split-fp16 GEMM --------------------------------
#define GSMEM (2 * 65536)
__global__ __launch_bounds__(512, 1) void gemm_mma(
    const __half* __restrict__ Ah, const __half* __restrict__ Al,
    const __half* __restrict__ Bh, const __half* __restrict__ Bl,
    const float* __restrict__ bias, int Kstr, int NC, int mode,
    __half* __restrict__ Ch, __half* __restrict__ Cl, int Cstr,
    float* __restrict__ Cf)
{
    extern __shared__ char smem[];
    const uint32_t sb = smem_u32(smem);
    const int tid = threadIdx.x;
    const int m0 = blockIdx.x << 7, n0 = blockIdx.y << 7;
    const int lane = tid & 31;
    const int wm = (tid >> 5) & 3, wn = tid >> 7;

    float acc[8][4];
    #pragma unroll
    for (int i = 0; i < 8; i++)
        #pragma unroll
        for (int j = 0; j < 4; j++) acc[i][j] = 0.f;

    auto issue = [&](int c) {
        uint32_t buf = (c & 1) ? 65536u : 0u;
        int kc0 = c << 6;
        int rloc = tid >> 3, q = tid & 7;
        #pragma unroll
        for (int it = 0; it < 8; it++) {
            const int region = it >> 1;
            int rr = ((it & 1) << 6) + rloc;
            const __half* src;
            if      (region == 0) src = Ah + (size_t)(m0 + rr) * Kstr + kc0 + q * 8;
            else if (region == 1) src = Al + (size_t)(m0 + rr) * Kstr + kc0 + q * 8;
            else if (region == 2) src = Bh + (size_t)(n0 + rr) * Kstr + kc0 + q * 8;
            else                  src = Bl + (size_t)(n0 + rr) * Kstr + kc0 + q * 8;
            uint32_t off = (uint32_t)(rr * 128 + q * 16);
            off ^= (off >> 3) & 0x70;
            CPASYNC16(sb + buf + region * 16384u + off, src);
        }
        asm volatile("cp.async.commit_group;" ::: "memory");
    };

    issue(0);
    for (int c = 0; c < NC; c++) {
        if (c + 1 < NC) {
            issue(c + 1);
            asm volatile("cp.async.wait_group 1;" ::: "memory");
        } else {
            asm volatile("cp.async.wait_group 0;" ::: "memory");
        }
        __syncthreads();
        const uint32_t buf = sb + ((c & 1) ? 65536u : 0u);

        #pragma unroll
        for (int ks = 0; ks < 4; ks++) {
            uint32_t ah[2][4], al2[2][4], bh[4][2], bl2[4][2];
            #pragma unroll
            for (int mi = 0; mi < 2; mi++) {
                uint32_t row = wm * 32 + mi * 16 + (lane & 15);
                uint32_t ch  = ks * 2 + (lane >> 4);
                uint32_t off = row * 128 + ch * 16;
                off ^= (off >> 3) & 0x70;
                LDM4(ah[mi],  buf + off);
                LDM4(al2[mi], buf + 16384u + off);
            }
            #pragma unroll
            for (int nj = 0; nj < 2; nj++) {
                uint32_t row = wn * 32 + nj * 16 + (lane & 7) + ((lane >> 4) << 3);
                uint32_t ch  = ks * 2 + ((lane >> 3) & 1);
                uint32_t off = row * 128 + ch * 16;
                off ^= (off >> 3) & 0x70;
                uint32_t r4[4];
                LDM4(r4, buf + 32768u + off);
                bh[nj * 2][0] = r4[0]; bh[nj * 2][1] = r4[1];
                bh[nj * 2 + 1][0] = r4[2]; bh[nj * 2 + 1][1] = r4[3];
                LDM4(r4, buf + 49152u + off);
                bl2[nj * 2][0] = r4[0]; bl2[nj * 2][1] = r4[1];
                bl2[nj * 2 + 1][0] = r4[2]; bl2[nj * 2 + 1][1] = r4[3];
            }
            #pragma unroll
            for (int mi = 0; mi < 2; mi++)
                #pragma unroll
                for (int nt = 0; nt < 4; nt++) {
                    float* C = acc[mi * 4 + nt];
                    MMA16816(C, ah[mi],  bh[nt]);
                    MMA16816(C, ah[mi],  bl2[nt]);
                    MMA16816(C, al2[mi], bh[nt]);
                }
        }
        __syncthreads();
    }

    float* cs = (float*)smem;
    #pragma unroll
    for (int mi = 0; mi < 2; mi++)
        #pragma unroll
        for (int nt = 0; nt < 4; nt++) {
            float* C = acc[mi * 4 + nt];
            int mrow = wm * 32 + mi * 16 + (lane >> 2);
            int ncol = wn * 32 + nt * 8 + 2 * (lane & 3);
            cs[ncol * 132 + mrow]           = C[0];
            cs[(ncol + 1) * 132 + mrow]     = C[1];
            cs[ncol * 132 + mrow + 8]       = C[2];
            cs[(ncol + 1) * 132 + mrow + 8] = C[3];
        }
    __syncthreads();

    if (mode) {
        #pragma unroll
        for (int it = 0; it < 16; it++) {
            int idx = it * 512 + tid;
            int n = idx >> 6, mp = idx & 63;
            float2 v2 = *(float2*)&cs[n * 132 + 2 * mp];
            float b0 = __ldg(bias + m0 + 2 * mp);
            float b1 = __ldg(bias + m0 + 2 * mp + 1);
            float v0 = fmaxf(v2.x + b0, 0.f);
            float v1 = fmaxf(v2.y + b1, 0.f);
            __half h0, l0, h1, l1;
            split_h(v0, h0, l0);
            split_h(v1, h1, l1);
            uint32_t ph = (uint32_t)__half_as_ushort(h0) |
                          ((uint32_t)__half_as_ushort(h1) << 16);
            uint32_t pl = (uint32_t)__half_as_ushort(l0) |
                          ((uint32_t)__half_as_ushort(l1) << 16);
            size_t o = (size_t)(n0 + n) * Cstr + m0 + 2 * mp;
            *(uint32_t*)(Ch + o) = ph;
            *(uint32_t*)(Cl + o) = pl;
        }
    } else {
        #pragma unroll
        for (int it = 0; it < 32; it++) {
            int idx = it * 512 + tid;
            int n = idx & 127, m = idx >> 7;
            float v = cs[n * 132 + m] + __ldg(bias + m0 + m);
            Cf[(size_t)(m0 + m) * FINAL + n0 + n] = v;
        }
    }
}

// ---------------- launch --------------------------------------------------
extern "C" void kernel_launch(void* const* d_in, const int* in_sizes, int n_in,
                              void* d_out, int out_size)
{
    const float* x        = (const float*)d_in[0];
    const float* w_causal = (const float*)d_in[1];
    const float* b_causal = (const float*)d_in[2];
    const float* w_tanh   = (const float*)d_in[3];
    const float* b_tanh   = (const float*)d_in[4];
    const float* w_sig    = (const float*)d_in[5];
    const float* b_sig    = (const float*)d_in[6];
    const float* w_skip   = (const float*)d_in[7];
    const float* b_skip   = (const float*)d_in[8];
    const float* w_dense  = (const float*)d_in[9];
    const float* b_dense  = (const float*)d_in[10];
    const float* w_post1  = (const float*)d_in[11];
    const float* b_post1  = (const float*)d_in[12];
    const float* w_post2  = (const float*)d_in[13];
    const float* b_post2  = (const float*)d_in[14];

    float *xa, *xb, *bsum;
    __half *Ghi, *Glo, *Shi, *Slo, *Hhi, *Hlo;
    __half *WaH, *WaL, *P1H, *P1L, *P2H, *P2L;
    cudaGetSymbolAddress((void**)&xa,  g_xa);
    cudaGetSymbolAddress((void**)&xb,  g_xb);
    cudaGetSymbolAddress((void**)&Ghi, g_Ghi);
    cudaGetSymbolAddress((void**)&Glo, g_Glo);
    cudaGetSymbolAddress((void**)&Shi, g_Shi);
    cudaGetSymbolAddress((void**)&Slo, g_Slo);
    cudaGetSymbolAddress((void**)&Hhi, g_Hhi);
    cudaGetSymbolAddress((void**)&Hlo, g_Hlo);
    cudaGetSymbolAddress((void**)&WaH, g_WaH);
    cudaGetSymbolAddress((void**)&WaL, g_WaL);
    cudaGetSymbolAddress((void**)&P1H, g_P1H);
    cudaGetSymbolAddress((void**)&P1L, g_P1L);
    cudaGetSymbolAddress((void**)&P2H, g_P2H);
    cudaGetSymbolAddress((void**)&P2L, g_P2L);
    cudaGetSymbolAddress((void**)&bsum, g_bsum);

    cudaFuncSetAttribute(gemm_mma,
                         cudaFuncAttributeMaxDynamicSharedMemorySize, GSMEM);

    prep_kernel<<<(SDIM * KPAD + 255) / 256, 256>>>(w_skip, b_skip, w_post1, w_post2);
    causal_kernel<<<(L0 + 255) / 256, 256>>>(x, w_causal, b_causal, xa);

    float* cur = xa;
    float* nxt = xb;
    int L = L0;
    for (int i = 0; i < NL; i++) {
        int d    = 1 << (i % 9);
        int Lout = L - 2 * d;
        int cut  = (Lout - FINAL) / 2;

        void (*kfn)(const float*, float*, const float*, const float*,
                    const float*, const float*, const float*, const float*,
                    __half*, __half*, int, int, int) = nullptr;
        int nt = 512;
        size_t smem = 0;
        switch (d) {
            case 1:   kfn = layer_kernel<1, 512>;   smem = LAYER_SMEM(1, 512);   break;
            case 2:   kfn = layer_kernel<2, 512>;   smem = LAYER_SMEM(2, 512);   break;
            case 4:   kfn = layer_kernel<4, 512>;   smem = LAYER_SMEM(4, 512);   break;
            case 8:   kfn = layer_kernel<8, 512>;   smem = LAYER_SMEM(8, 512);   break;
            case 16:  kfn = layer_kernel<16, 512>;  smem = LAYER_SMEM(16, 512);  break;
            case 32:  kfn = layer_kernel<32, 512>;  smem = LAYER_SMEM(32, 512);  break;
            case 64:  kfn = layer_kernel<64, 512>;  smem = LAYER_SMEM(64, 512);  break;
            case 128: kfn = layer_kernel<128, 512>; smem = LAYER_SMEM(128, 512); break;
            case 256: kfn = layer_kernel<256, 256>; smem = LAYER_SMEM(256, 256); nt = 256; break;
        }
        cudaFuncSetAttribute(kfn, cudaFuncAttributeMaxDynamicSharedMemorySize,
                             (int)smem);
        kfn<<<(Lout + nt - 1) / nt, nt, smem>>>(
            cur, nxt,
            w_tanh  + (size_t)i * 3072, b_tanh  + i * 32,
            w_sig   + (size_t)i * 3072, b_sig   + i * 32,
            w_dense + (size_t)i * 1024, b_dense + i * 32,
            Ghi + i * 32, Glo + i * 32,
            L, Lout, cut);
        float* t = cur; cur = nxt; nxt = t;
        L = Lout;
    }

    // skip GEMM: S = relu(Wall @ G + bsum)   M=512, K=1472, N=160000
    gemm_mma<<<dim3(SDIM / 128, FINAL / 128), 512, GSMEM>>>(
        WaH, WaL, Ghi, Glo, bsum, KPAD, KPAD / 64, 1, Shi, Slo, SDIM, nullptr);
    // post1: H = relu(W1 @ S + b1)           M=512, K=512
    gemm_mma<<<dim3(SDIM / 128, FINAL / 128), 512, GSMEM>>>(
        P1H, P1L, Shi, Slo, b_post1, SDIM, SDIM / 64, 1, Hhi, Hlo, SDIM, nullptr);
    // post2: out = W2 @ H + b2               M=256, K=512, fp32 channel-major
    gemm_mma<<<dim3(QDIM / 128, FINAL / 128), 512, GSMEM>>>(
        P2H, P2L, Hhi, Hlo, b_post2, SDIM, SDIM / 64, 0, nullptr, nullptr, 0,
        (float*)d_out);
}

// round 5
// speedup vs baseline: 3.6506x; 1.8489x over previous
#include <cuda_runtime.h>
#include <cuda_fp16.h>
#include <cstdint>

#define L_INPUT 165142
#define KFILT   33
#define L0      (L_INPUT - KFILT + 1)   /* 165110 */
#define RDC     32
#define SDIM    512
#define QDIM    256
#define NL      45
#define FINAL   160000
#define KPAD    1472                    /* 45*32=1440 padded to 64-multiple */

// ---------------- scratch (static device globals; no allocation allowed) ----
// residual stream, time-major [t][32ch], fp16 hi/lo
__device__ __half g_xah[(size_t)L0 * 32];
__device__ __half g_xal[(size_t)L0 * 32];
__device__ __half g_xbh[(size_t)L0 * 32];
__device__ __half g_xbl[(size_t)L0 * 32];
// time-major activation buffers, fp16 hi/lo split (zero-init, pads stay 0)
__device__ __half g_Ghi[(size_t)FINAL * KPAD];
__device__ __half g_Glo[(size_t)FINAL * KPAD];
__device__ __half g_Shi[(size_t)FINAL * SDIM];
__device__ __half g_Slo[(size_t)FINAL * SDIM];
__device__ __half g_Hhi[(size_t)FINAL * SDIM];
__device__ __half g_Hlo[(size_t)FINAL * SDIM];
// split weights for big GEMMs
__device__ __half g_WaH[SDIM * KPAD];
__device__ __half g_WaL[SDIM * KPAD];
__device__ __half g_P1H[SDIM * SDIM];
__device__ __half g_P1L[SDIM * SDIM];
__device__ __half g_P2H[QDIM * SDIM];
__device__ __half g_P2L[QDIM * SDIM];
__device__ float g_bsum[SDIM];

// ---------------- helpers --------------------------------------------------
static __device__ __forceinline__ uint32_t smem_u32(const void* p) {
    uint32_t a;
    asm("{ .reg .u64 t; cvta.to.shared.u64 t, %1; cvt.u32.u64 %0, t; }"
        : "=r"(a) : "l"(p));
    return a;
}
static __device__ __forceinline__ void split_h(float v, __half& h, __half& l) {
    h = __float2half(v);
    l = __float2half(v - __half2float(h));
}
// swizzled smem offset within a [rows][64B] tile (16B chunk q in 0..3)
static __device__ __forceinline__ uint32_t sw(int t, int q) {
    return (uint32_t)((t << 6) + (((q ^ ((t >> 1) & 3))) << 4));
}

#define LDM4(R, a) \
    asm volatile("ldmatrix.sync.aligned.m8n8.x4.shared.b16 {%0,%1,%2,%3}, [%4];" \
        : "=r"((R)[0]), "=r"((R)[1]), "=r"((R)[2]), "=r"((R)[3]) : "r"(a))

#define MMA16816(C, A, B) \
    asm volatile("mma.sync.aligned.m16n8k16.row.col.f32.f16.f16.f32 " \
        "{%0,%1,%2,%3}, {%4,%5,%6,%7}, {%8,%9}, {%0,%1,%2,%3};" \
        : "+f"((C)[0]), "+f"((C)[1]), "+f"((C)[2]), "+f"((C)[3]) \
        : "r"((A)[0]), "r"((A)[1]), "r"((A)[2]), "r"((A)[3]), \
          "r"((B)[0]), "r"((B)[1]))

#define CPASYNC16(dst, src) \
    asm volatile("cp.async.cg.shared.global [%0], [%1], 16;" \
        :: "r"(dst), "l"(src) : "memory")

// ---------------- prep: split weights for big GEMMs, sum skip bias --------
__global__ __launch_bounds__(256) void prep_kernel(const float* __restrict__ wskip,
                                                   const float* __restrict__ bskip,
                                                   const float* __restrict__ wp1,
                                                   const float* __restrict__ wp2)
{
    int idx = blockIdx.x * 256 + threadIdx.x;
    if (idx < SDIM * KPAD) {
        int c = idx / KPAD, k = idx - c * KPAD;
        float v = 0.f;
        if (k < NL * RDC) {
            int i = k >> 5, r = k & 31;
            v = wskip[(size_t)i * SDIM * RDC + (size_t)c * RDC + r];
        }
        split_h(v, g_WaH[idx], g_WaL[idx]);
    }
    if (idx < SDIM * SDIM) split_h(wp1[idx], g_P1H[idx], g_P1L[idx]);
    if (idx < QDIM * SDIM) split_h(wp2[idx], g_P2H[idx], g_P2L[idx]);
    if (idx < SDIM) {
        float s = 0.f;
        #pragma unroll
        for (int i = 0; i < NL; i++) s += bskip[i * SDIM + idx];
        g_bsum[idx] = s;
    }
}

// ---------------- causal conv: 1 -> 32 ch, K=33; out time-major hi/lo ------
__global__ __launch_bounds__(256) void causal_kernel(const float* __restrict__ x,
                                                     const float* __restrict__ w,
                                                     const float* __restrict__ b,
                                                     __half* __restrict__ oh,
                                                     __half* __restrict__ ol)
{
    __shared__ float xsh[256 + KFILT - 1];
    __shared__ float wsh[KFILT * 32];
    __shared__ float bsh[32];
    int tid = threadIdx.x;
    int t0  = blockIdx.x * 256;

    for (int i = tid; i < 256 + KFILT - 1; i += 256) {
        int g = t0 + i;
        xsh[i] = (g < L_INPUT) ? x[g] : 0.f;
    }
    for (int i = tid; i < 32 * KFILT; i += 256) {
        int c = i / KFILT, k = i - c * KFILT;
        wsh[k * 32 + c] = w[i];
    }
    if (tid < 32) bsh[tid] = b[tid];
    __syncthreads();

    int c = tid & 31, lane = tid >> 5;
    for (int grp = 0; grp < 4; grp++) {
        int tl = lane * 32 + grp * 8;
        float acc[8];
        #pragma unroll
        for (int u = 0; u < 8; u++) acc[u] = bsh[c];
        #pragma unroll
        for (int k = 0; k < KFILT; k++) {
            float wv = wsh[k * 32 + c];
            #pragma unroll
            for (int u = 0; u < 8; u++) acc[u] += wv * xsh[tl + u + k];
        }
        #pragma unroll
        for (int u = 0; u < 8; u++) {
            int t = t0 + tl + u;
            if (t < L0) {
                __half h, l;
                split_h(acc[u], h, l);
                oh[(size_t)t * 32 + c] = h;
                ol[(size_t)t * 32 + c] = l;
            }
        }
    }
}

// ---------------- tensor-core dilated residual layer -----------------------
// 384 threads = 12 warps; each warp owns a 64(M) x 32(time) gate tile and a
// 32 x 32 dense tile. x stream is time-major fp16 hi/lo.
template<int D>
__global__ __launch_bounds__(384, 1) void layer_mma(
    const __half* __restrict__ xinh, const __half* __restrict__ xinl,
    __half* __restrict__ xouth, __half* __restrict__ xoutl,
    const float* __restrict__ wt, const float* __restrict__ bt,
    const float* __restrict__ ws, const float* __restrict__ bs,
    const float* __restrict__ wd, const float* __restrict__ bd,
    __half* __restrict__ Gh, __half* __restrict__ Gl,
    int L_in, int L_out, int cut)
{
    constexpr int NT = 384;
    constexpr int RT = NT + 2 * D;
    // byte offsets in dynamic smem
    constexpr int XH  = 0;
    constexpr int XL  = RT * 64;
    constexpr int AGH = 2 * RT * 64;         // 3 taps x 64 rows x 64B
    constexpr int AGL = AGH + 12288;
    constexpr int ADH = AGL + 12288;         // 32 rows x 64B
    constexpr int ADL = ADH + 2048;
    constexpr int GHo = ADL + 2048;          // NT rows x 64B
    constexpr int GLo = GHo + NT * 64;
    constexpr int BIA = GLo + NT * 64;       // 96 floats

    extern __shared__ char smem[];
    const uint32_t sb = smem_u32(smem);
    const int tid = threadIdx.x;
    const int t0  = blockIdx.x * NT;

    // ---- x tile (contiguous global rows -> swizzled smem) ----
    for (int idx = tid; idx < RT * 4; idx += NT) {
        int t = idx >> 2, q = idx & 3;
        uint32_t so = sw(t, q);
        if (t0 + t < L_in) {
            CPASYNC16(sb + XH + so, xinh + (size_t)(t0 + t) * 32 + q * 8);
            CPASYNC16(sb + XL + so, xinl + (size_t)(t0 + t) * 32 + q * 8);
        } else {
            uint4 z = make_uint4(0, 0, 0, 0);
            *(uint4*)(smem + XH + so) = z;
            *(uint4*)(smem + XL + so) = z;
        }
    }
    asm volatile("cp.async.commit_group;" ::: "memory");

    // ---- weights into smem (split on the fly) ----
    for (int idx = tid; idx < 6144; idx += NT) {
        int m = idx / 96, rem = idx - m * 96, r = rem / 3, j = rem - r * 3;
        float v = (m < 32) ? wt[m * 96 + r * 3 + j] : ws[(m - 32) * 96 + r * 3 + j];
        __half h, l;
        split_h(v, h, l);
        uint32_t off = (uint32_t)(j * 4096) + sw(m, r >> 3) + (r & 7) * 2;
        *(__half*)(smem + AGH + off) = h;
        *(__half*)(smem + AGL + off) = l;
    }
    for (int idx = tid; idx < 1024; idx += NT) {
        int c = idx >> 5, r = idx & 31;
        __half h, l;
        split_h(wd[idx], h, l);
        uint32_t off = sw(c, r >> 3) + (r & 7) * 2;
        *(__half*)(smem + ADH + off) = h;
        *(__half*)(smem + ADL + off) = l;
    }
    {
        float* bia = (float*)(smem + BIA);
        if (tid < 32) {
            bia[tid]      = bt[tid];
            bia[32 + tid] = bs[tid];
            bia[64 + tid] = bd[tid];
        }
    }
    asm volatile("cp.async.wait_group 0;" ::: "memory");
    __syncthreads();

    const int l    = tid & 31;
    const int w    = tid >> 5;
    const int grp  = l >> 3, mrow = l & 7;
    const int tw   = w * 32;
    const float* bia = (const float*)(smem + BIA);

    // ---- gate GEMM: C[64 x 32] ----
    float acc[4][4][4];
    #pragma unroll
    for (int mi = 0; mi < 4; mi++) {
        float b0 = bia[mi * 16 + (l >> 2)];
        float b8 = bia[mi * 16 + (l >> 2) + 8];
        #pragma unroll
        for (int ni = 0; ni < 4; ni++) {
            acc[mi][ni][0] = b0; acc[mi][ni][1] = b0;
            acc[mi][ni][2] = b8; acc[mi][ni][3] = b8;
        }
    }

    #pragma unroll
    for (int j = 0; j < 3; j++) {
        #pragma unroll
        for (int kc = 0; kc < 2; kc++) {
            uint32_t a4[4][4], b1[4][2], b2[4][2];
            #pragma unroll
            for (int h2 = 0; h2 < 2; h2++) {
                int t = tw + j * D + h2 * 16 + ((grp >> 1) << 3) + mrow;
                int q = kc * 2 + (grp & 1);
                uint32_t R[4];
                LDM4(R, sb + XH + sw(t, q));
                b1[h2 * 2][0] = R[0]; b1[h2 * 2][1] = R[1];
                b1[h2 * 2 + 1][0] = R[2]; b1[h2 * 2 + 1][1] = R[3];
                LDM4(R, sb + XL + sw(t, q));
                b2[h2 * 2][0] = R[0]; b2[h2 * 2][1] = R[1];
                b2[h2 * 2 + 1][0] = R[2]; b2[h2 * 2 + 1][1] = R[3];
            }
            int tm = ((grp & 1) << 3) + mrow;
            int qa = kc * 2 + (grp >> 1);
            #pragma unroll
            for (int mi = 0; mi < 4; mi++)
                LDM4(a4[mi], sb + AGH + j * 4096 + sw(mi * 16 + tm, qa));
            #pragma unroll
            for (int mi = 0; mi < 4; mi++)
                #pragma unroll
                for (int ni = 0; ni < 4; ni++) {
                    MMA16816(acc[mi][ni], a4[mi], b1[ni]);
                    MMA16816(acc[mi][ni], a4[mi], b2[ni]);
                }
            #pragma unroll
            for (int mi = 0; mi < 4; mi++)
                LDM4(a4[mi], sb + AGL + j * 4096 + sw(mi * 16 + tm, qa));
            #pragma unroll
            for (int mi = 0; mi < 4; mi++)
                #pragma unroll
                for (int ni = 0; ni < 4; ni++)
                    MMA16816(acc[mi][ni], a4[mi], b1[ni]);
        }
    }

    // ---- activation + g to smem (hi/lo) ----
    #pragma unroll
    for (int mi = 0; mi < 2; mi++)
        #pragma unroll
        for (int ni = 0; ni < 4; ni++)
            #pragma unroll
            for (int jj = 0; jj < 4; jj++) {
                float a1 = fminf(fmaxf(acc[mi][ni][jj], -30.f), 30.f);
                float a2 = fminf(fmaxf(acc[mi + 2][ni][jj], -30.f), 30.f);
                float u  = 1.f + __expf(-2.f * a1);
                float vv = 1.f + __expf(-a2);
                float gv = __fdividef(2.f - u, u * vv);
                int t_loc = tw + ni * 8 + 2 * (l & 3) + (jj & 1);
                int c     = mi * 16 + (l >> 2) + ((jj >= 2) ? 8 : 0);
                __half h, lo2;
                split_h(gv, h, lo2);
                uint32_t off = sw(t_loc, c >> 3) + (c & 7) * 2;
                *(__half*)(smem + GHo + off) = h;
                *(__half*)(smem + GLo + off) = lo2;
            }
    __syncwarp();

    // ---- G copy out (one row per lane) ----
    {
        int row = tw + l;
        int uo  = t0 + row - cut;
        if (uo >= 0 && uo < FINAL) {
            char* dh = (char*)(Gh + (size_t)uo * KPAD);
            char* dl = (char*)(Gl + (size_t)uo * KPAD);
            #pragma unroll
            for (int q = 0; q < 4; q++) {
                *(uint4*)(dh + q * 16) = *(uint4*)(smem + GHo + sw(row, q));
                *(uint4*)(dl + q * 16) = *(uint4*)(smem + GLo + sw(row, q));
            }
        }
    }

    // ---- dense GEMM: 32 x 32 ----
    float dacc[2][4][4];
    #pragma unroll
    for (int mi = 0; mi < 2; mi++) {
        float b0 = bia[64 + mi * 16 + (l >> 2)];
        float b8 = bia[64 + mi * 16 + (l >> 2) + 8];
        #pragma unroll
        for (int ni = 0; ni < 4; ni++) {
            dacc[mi][ni][0] = b0; dacc[mi][ni][1] = b0;
            dacc[mi][ni][2] = b8; dacc[mi][ni][3] = b8;
        }
    }
    #pragma unroll
    for (int kc = 0; kc < 2; kc++) {
        uint32_t a4[2][4], b1[4][2], b2[4][2];
        #pragma unroll
        for (int h2 = 0; h2 < 2; h2++) {
            int t = tw + h2 * 16 + ((grp >> 1) << 3) + mrow;
            int q = kc * 2 + (grp & 1);
            uint32_t R[4];
            LDM4(R, sb + GHo + sw(t, q));
            b1[h2 * 2][0] = R[0]; b1[h2 * 2][1] = R[1];
            b1[h2 * 2 + 1][0] = R[2]; b1[h2 * 2 + 1][1] = R[3];
            LDM4(R, sb + GLo + sw(t, q));
            b2[h2 * 2][0] = R[0]; b2[h2 * 2][1] = R[1];
            b2[h2 * 2 + 1][0] = R[2]; b2[h2 * 2 + 1][1] = R[3];
        }
        int tm = ((grp & 1) << 3) + mrow;
        int qa = kc * 2 + (grp >> 1);
        #pragma unroll
        for (int mi = 0; mi < 2; mi++)
            LDM4(a4[mi], sb + ADH + sw(mi * 16 + tm, qa));
        #pragma unroll
        for (int mi = 0; mi < 2; mi++)
            #pragma unroll
            for (int ni = 0; ni < 4; ni++) {
                MMA16816(dacc[mi][ni], a4[mi], b1[ni]);
                MMA16816(dacc[mi][ni], a4[mi], b2[ni]);
            }
        #pragma unroll
        for (int mi = 0; mi < 2; mi++)
            LDM4(a4[mi], sb + ADL + sw(mi * 16 + tm, qa));
        #pragma unroll
        for (int mi = 0; mi < 2; mi++)
            #pragma unroll
            for (int ni = 0; ni < 4; ni++)
                MMA16816(dacc[mi][ni], a4[mi], b1[ni]);
    }
    __syncwarp();

    // ---- residual add + re-split into staging (reuse g tile) ----
    #pragma unroll
    for (int mi = 0; mi < 2; mi++)
        #pragma unroll
        for (int ni = 0; ni < 4; ni++)
            #pragma unroll
            for (int jj = 0; jj < 4; jj++) {
                int t_loc = tw + ni * 8 + 2 * (l & 3) + (jj & 1);
                int c     = mi * 16 + (l >> 2) + ((jj >= 2) ? 8 : 0);
                uint32_t offx = sw(t_loc + D, c >> 3) + (c & 7) * 2;
                float xv = __half2float(*(__half*)(smem + XH + offx))
                         + __half2float(*(__half*)(smem + XL + offx));
                float ov = dacc[mi][ni][jj] + xv;
                __half h, lo2;
                split_h(ov, h, lo2);
                uint32_t off = sw(t_loc, c >> 3) + (c & 7) * 2;
                *(__half*)(smem + GHo + off) = h;
                *(__half*)(smem + GLo + off) = lo2;
            }
    __syncwarp();

    // ---- xout copy (one row per lane) ----
    {
        int row = tw + l;
        int t   = t0 + row;
        if (t < L_out) {
            char* dh = (char*)(xouth + (size_t)t * 32);
            char* dl = (char*)(xoutl + (size_t)t * 32);
            #pragma unroll
            for (int q = 0; q < 4; q++) {
                *(uint4*)(dh + q * 16) = *(uint4*)(smem + GHo + sw(row, q));
                *(uint4*)(dl + q * 16) = *(uint4*)(smem + GLo + sw(row, q));
            }
        }
    }
}

#define LAYER_SMEM_B(D_) (2 * (384 + 2 * (D_)) * 64 + 12288 * 2 + 2048 * 2 \
                          + 384 * 64 * 2 + 384)

// ---------------- mma.sync split-fp16 GEMM (unchanged, known-good) --------
#define GSMEM (2 * 65536)
__global__ __launch_bounds__(512, 1) void gemm_mma(
    const __half* __restrict__ Ah, const __half* __restrict__ Al,
    const __half* __restrict__ Bh, const __half* __restrict__ Bl,
    const float* __restrict__ bias, int Kstr, int NC, int mode,
    __half* __restrict__ Ch, __half* __restrict__ Cl, int Cstr,
    float* __restrict__ Cf)
{
    extern __shared__ char smem[];
    const uint32_t sb = smem_u32(smem);
    const int tid = threadIdx.x;
    const int m0 = blockIdx.x << 7, n0 = blockIdx.y << 7;
    const int lane = tid & 31;
    const int wm = (tid >> 5) & 3, wn = tid >> 7;

    float acc[8][4];
    #pragma unroll
    for (int i = 0; i < 8; i++)
        #pragma unroll
        for (int j = 0; j < 4; j++) acc[i][j] = 0.f;

    auto issue = [&](int c) {
        uint32_t buf = (c & 1) ? 65536u : 0u;
        int kc0 = c << 6;
        int rloc = tid >> 3, q = tid & 7;
        #pragma unroll
        for (int it = 0; it < 8; it++) {
            const int region = it >> 1;
            int rr = ((it & 1) << 6) + rloc;
            const __half* src;
            if      (region == 0) src = Ah + (size_t)(m0 + rr) * Kstr + kc0 + q * 8;
            else if (region == 1) src = Al + (size_t)(m0 + rr) * Kstr + kc0 + q * 8;
            else if (region == 2) src = Bh + (size_t)(n0 + rr) * Kstr + kc0 + q * 8;
            else                  src = Bl + (size_t)(n0 + rr) * Kstr + kc0 + q * 8;
            uint32_t off = (uint32_t)(rr * 128 + q * 16);
            off ^= (off >> 3) & 0x70;
            CPASYNC16(sb + buf + region * 16384u + off, src);
        }
        asm volatile("cp.async.commit_group;" ::: "memory");
    };

    issue(0);
    for (int c = 0; c < NC; c++) {
        if (c + 1 < NC) {
            issue(c + 1);
            asm volatile("cp.async.wait_group 1;" ::: "memory");
        } else {
            asm volatile("cp.async.wait_group 0;" ::: "memory");
        }
        __syncthreads();
        const uint32_t buf = sb + ((c & 1) ? 65536u : 0u);

        #pragma unroll
        for (int ks = 0; ks < 4; ks++) {
            uint32_t ah[2][4], al2[2][4], bh[4][2], bl2[4][2];
            #pragma unroll
            for (int mi = 0; mi < 2; mi++) {
                uint32_t row = wm * 32 + mi * 16 + (lane & 15);
                uint32_t ch  = ks * 2 + (lane >> 4);
                uint32_t off = row * 128 + ch * 16;
                off ^= (off >> 3) & 0x70;
                LDM4(ah[mi],  buf + off);
                LDM4(al2[mi], buf + 16384u + off);
            }
            #pragma unroll
            for (int nj = 0; nj < 2; nj++) {
                uint32_t row = wn * 32 + nj * 16 + (lane & 7) + ((lane >> 4) << 3);
                uint32_t ch  = ks * 2 + ((lane >> 3) & 1);
                uint32_t off = row * 128 + ch * 16;
                off ^= (off >> 3) & 0x70;
                uint32_t r4[4];
                LDM4(r4, buf + 32768u + off);
                bh[nj * 2][0] = r4[0]; bh[nj * 2][1] = r4[1];
                bh[nj * 2 + 1][0] = r4[2]; bh[nj * 2 + 1][1] = r4[3];
                LDM4(r4, buf + 49152u + off);
                bl2[nj * 2][0] = r4[0]; bl2[nj * 2][1] = r4[1];
                bl2[nj * 2 + 1][0] = r4[2]; bl2[nj * 2 + 1][1] = r4[3];
            }
            #pragma unroll
            for (int mi = 0; mi < 2; mi++)
                #pragma unroll
                for (int nt = 0; nt < 4; nt++) {
                    float* C = acc[mi * 4 + nt];
                    MMA16816(C, ah[mi],  bh[nt]);
                    MMA16816(C, ah[mi],  bl2[nt]);
                    MMA16816(C, al2[mi], bh[nt]);
                }
        }
        __syncthreads();
    }

    float* cs = (float*)smem;
    #pragma unroll
    for (int mi = 0; mi < 2; mi++)
        #pragma unroll
        for (int nt = 0; nt < 4; nt++) {
            float* C = acc[mi * 4 + nt];
            int mrow = wm * 32 + mi * 16 + (lane >> 2);
            int ncol = wn * 32 + nt * 8 + 2 * (lane & 3);
            cs[ncol * 132 + mrow]           = C[0];
            cs[(ncol + 1) * 132 + mrow]     = C[1];
            cs[ncol * 132 + mrow + 8]       = C[2];
            cs[(ncol + 1) * 132 + mrow + 8] = C[3];
        }
    __syncthreads();

    if (mode) {
        #pragma unroll
        for (int it = 0; it < 16; it++) {
            int idx = it * 512 + tid;
            int n = idx >> 6, mp = idx & 63;
            float2 v2 = *(float2*)&cs[n * 132 + 2 * mp];
            float b0 = __ldg(bias + m0 + 2 * mp);
            float b1 = __ldg(bias + m0 + 2 * mp + 1);
            float v0 = fmaxf(v2.x + b0, 0.f);
            float v1 = fmaxf(v2.y + b1, 0.f);
            __half h0, l0, h1, l1;
            split_h(v0, h0, l0);
            split_h(v1, h1, l1);
            uint32_t ph = (uint32_t)__half_as_ushort(h0) |
                          ((uint32_t)__half_as_ushort(h1) << 16);
            uint32_t pl = (uint32_t)__half_as_ushort(l0) |
                          ((uint32_t)__half_as_ushort(l1) << 16);
            size_t o = (size_t)(n0 + n) * Cstr + m0 + 2 * mp;
            *(uint32_t*)(Ch + o) = ph;
            *(uint32_t*)(Cl + o) = pl;
        }
    } else {
        #pragma unroll
        for (int it = 0; it < 32; it++) {
            int idx = it * 512 + tid;
            int n = idx & 127, m = idx >> 7;
            float v = cs[n * 132 + m] + __ldg(bias + m0 + m);
            Cf[(size_t)(m0 + m) * FINAL + n0 + n] = v;
        }
    }
}

// ---------------- launch --------------------------------------------------
extern "C" void kernel_launch(void* const* d_in, const int* in_sizes, int n_in,
                              void* d_out, int out_size)
{
    const float* x        = (const float*)d_in[0];
    const float* w_causal = (const float*)d_in[1];
    const float* b_causal = (const float*)d_in[2];
    const float* w_tanh   = (const float*)d_in[3];
    const float* b_tanh   = (const float*)d_in[4];
    const float* w_sig    = (const float*)d_in[5];
    const float* b_sig    = (const float*)d_in[6];
    const float* w_skip   = (const float*)d_in[7];
    const float* b_skip   = (const float*)d_in[8];
    const float* w_dense  = (const float*)d_in[9];
    const float* b_dense  = (const float*)d_in[10];
    const float* w_post1  = (const float*)d_in[11];
    const float* b_post1  = (const float*)d_in[12];
    const float* w_post2  = (const float*)d_in[13];
    const float* b_post2  = (const float*)d_in[14];

    float *bsum;
    __half *xah, *xal, *xbh, *xbl;
    __half *Ghi, *Glo, *Shi, *Slo, *Hhi, *Hlo;
    __half *WaH, *WaL, *P1H, *P1L, *P2H, *P2L;
    cudaGetSymbolAddress((void**)&xah, g_xah);
    cudaGetSymbolAddress((void**)&xal, g_xal);
    cudaGetSymbolAddress((void**)&xbh, g_xbh);
    cudaGetSymbolAddress((void**)&xbl, g_xbl);
    cudaGetSymbolAddress((void**)&Ghi, g_Ghi);
    cudaGetSymbolAddress((void**)&Glo, g_Glo);
    cudaGetSymbolAddress((void**)&Shi, g_Shi);
    cudaGetSymbolAddress((void**)&Slo, g_Slo);
    cudaGetSymbolAddress((void**)&Hhi, g_Hhi);
    cudaGetSymbolAddress((void**)&Hlo, g_Hlo);
    cudaGetSymbolAddress((void**)&WaH, g_WaH);
    cudaGetSymbolAddress((void**)&WaL, g_WaL);
    cudaGetSymbolAddress((void**)&P1H, g_P1H);
    cudaGetSymbolAddress((void**)&P1L, g_P1L);
    cudaGetSymbolAddress((void**)&P2H, g_P2H);
    cudaGetSymbolAddress((void**)&P2L, g_P2L);
    cudaGetSymbolAddress((void**)&bsum, g_bsum);

    cudaFuncSetAttribute(gemm_mma,
                         cudaFuncAttributeMaxDynamicSharedMemorySize, GSMEM);

    prep_kernel<<<(SDIM * KPAD + 255) / 256, 256>>>(w_skip, b_skip, w_post1, w_post2);
    causal_kernel<<<(L0 + 255) / 256, 256>>>(x, w_causal, b_causal, xah, xal);

    __half *curh = xah, *curl = xal, *nxth = xbh, *nxtl = xbl;
    int L = L0;
    for (int i = 0; i < NL; i++) {
        int d    = 1 << (i % 9);
        int Lout = L - 2 * d;
        int cut  = (Lout - FINAL) / 2;

        void (*kfn)(const __half*, const __half*, __half*, __half*,
                    const float*, const float*, const float*, const float*,
                    const float*, const float*, __half*, __half*,
                    int, int, int) = nullptr;
        size_t smem = 0;
        switch (d) {
            case 1:   kfn = layer_mma<1>;   smem = LAYER_SMEM_B(1);   break;
            case 2:   kfn = layer_mma<2>;   smem = LAYER_SMEM_B(2);   break;
            case 4:   kfn = layer_mma<4>;   smem = LAYER_SMEM_B(4);   break;
            case 8:   kfn = layer_mma<8>;   smem = LAYER_SMEM_B(8);   break;
            case 16:  kfn = layer_mma<16>;  smem = LAYER_SMEM_B(16);  break;
            case 32:  kfn = layer_mma<32>;  smem = LAYER_SMEM_B(32);  break;
            case 64:  kfn = layer_mma<64>;  smem = LAYER_SMEM_B(64);  break;
            case 128: kfn = layer_mma<128>; smem = LAYER_SMEM_B(128); break;
            case 256: kfn = layer_mma<256>; smem = LAYER_SMEM_B(256); break;
        }
        cudaFuncSetAttribute(kfn, cudaFuncAttributeMaxDynamicSharedMemorySize,
                             (int)smem);
        kfn<<<(Lout + 383) / 384, 384, smem>>>(
            curh, curl, nxth, nxtl,
            w_tanh  + (size_t)i * 3072, b_tanh  + i * 32,
            w_sig   + (size_t)i * 3072, b_sig   + i * 32,
            w_dense + (size_t)i * 1024, b_dense + i * 32,
            Ghi + i * 32, Glo + i * 32,
            L, Lout, cut);
        __half* t;
        t = curh; curh = nxth; nxth = t;
        t = curl; curl = nxtl; nxtl = t;
        L = Lout;
    }

    // skip GEMM: S = relu(Wall @ G + bsum)   M=512, K=1472, N=160000
    gemm_mma<<<dim3(SDIM / 128, FINAL / 128), 512, GSMEM>>>(
        WaH, WaL, Ghi, Glo, bsum, KPAD, KPAD / 64, 1, Shi, Slo, SDIM, nullptr);
    // post1: H = relu(W1 @ S + b1)           M=512, K=512
    gemm_mma<<<dim3(SDIM / 128, FINAL / 128), 512, GSMEM>>>(
        P1H, P1L, Shi, Slo, b_post1, SDIM, SDIM / 64, 1, Hhi, Hlo, SDIM, nullptr);
    // post2: out = W2 @ H + b2               M=256, K=512, fp32 channel-major
    gemm_mma<<<dim3(QDIM / 128, FINAL / 128), 512, GSMEM>>>(
        P2H, P2L, Hhi, Hlo, b_post2, SDIM, SDIM / 64, 0, nullptr, nullptr, 0,
        (float*)d_out);
}